// round 8
// baseline (speedup 1.0000x reference)
#include <cuda_runtime.h>
#include <cuda_fp16.h>

#define DINL __device__ __forceinline__

constexpr int S = 2048, D = 1024, H = 16, NBATCH = 2, DK = 64;
constexpr int M = NBATCH * S;  // 4096 rows

// ---- scratch offsets (halves) ----
constexpr size_t OFF_QH = 0;
constexpr size_t OFF_KH = OFF_QH + (size_t)M * D;
constexpr size_t OFF_VH = OFF_KH + (size_t)M * D;
constexpr size_t OFF_WQ = OFF_VH + (size_t)M * D;
constexpr size_t OFF_WK = OFF_WQ + (size_t)D * D;
constexpr size_t OFF_WV = OFF_WK + (size_t)D * D;
constexpr size_t OFF_WO = OFF_WV + (size_t)D * D;
constexpr size_t OFF_PE = OFF_WO + (size_t)D * D;     // pe_rev [S][64]
constexpr size_t OFF_Q  = OFF_PE + (size_t)S * DK;    // [bh][s][dk] (pre-scaled by 1/8)
constexpr size_t OFF_K  = OFF_Q + (size_t)M * D;
constexpr size_t OFF_V  = OFF_K + (size_t)M * D;
constexpr size_t OFF_AO = OFF_V + (size_t)M * D;      // [b*S+s][h*64+d]
constexpr size_t BUF_TOTAL = OFF_AO + (size_t)M * D;

__device__ __align__(256) __half g_buf[BUF_TOTAL];

// ---- PTX helpers ----
DINL void ldsm_a(unsigned (&r)[4], const void* p) {
    unsigned a = (unsigned)__cvta_generic_to_shared(p);
    asm volatile("ldmatrix.sync.aligned.m8n8.x4.shared.b16 {%0,%1,%2,%3}, [%4];"
                 : "=r"(r[0]), "=r"(r[1]), "=r"(r[2]), "=r"(r[3]) : "r"(a));
}
DINL void ldsm_a_u(unsigned (&r)[4], unsigned a) {
    asm volatile("ldmatrix.sync.aligned.m8n8.x4.shared.b16 {%0,%1,%2,%3}, [%4];"
                 : "=r"(r[0]), "=r"(r[1]), "=r"(r[2]), "=r"(r[3]) : "r"(a));
}
DINL void ldsm_bt(unsigned (&r)[4], const void* p) {
    unsigned a = (unsigned)__cvta_generic_to_shared(p);
    asm volatile("ldmatrix.sync.aligned.m8n8.x4.trans.shared.b16 {%0,%1,%2,%3}, [%4];"
                 : "=r"(r[0]), "=r"(r[1]), "=r"(r[2]), "=r"(r[3]) : "r"(a));
}
DINL void ldsm_bt_u(unsigned (&r)[4], unsigned a) {
    asm volatile("ldmatrix.sync.aligned.m8n8.x4.trans.shared.b16 {%0,%1,%2,%3}, [%4];"
                 : "=r"(r[0]), "=r"(r[1]), "=r"(r[2]), "=r"(r[3]) : "r"(a));
}
DINL void mma16816(float (&c)[4], const unsigned (&a)[4], unsigned b0, unsigned b1) {
    asm volatile(
        "mma.sync.aligned.m16n8k16.row.col.f32.f16.f16.f32 "
        "{%0,%1,%2,%3}, {%4,%5,%6,%7}, {%8,%9}, {%0,%1,%2,%3};"
        : "+f"(c[0]), "+f"(c[1]), "+f"(c[2]), "+f"(c[3])
        : "r"(a[0]), "r"(a[1]), "r"(a[2]), "r"(a[3]), "r"(b0), "r"(b1));
}
DINL unsigned packh2(float x, float y) {
    __half2 h = __floats2half2_rn(x, y);
    return *reinterpret_cast<unsigned*>(&h);
}
DINL void cp_async16(void* dst, const void* src) {
    unsigned d = (unsigned)__cvta_generic_to_shared(dst);
    asm volatile("cp.async.cg.shared.global [%0], [%1], 16;" :: "r"(d), "l"(src));
}

// ============================ fused converts ============================
__global__ void convert_all_kernel(
    const float* __restrict__ q, const float* __restrict__ k, const float* __restrict__ v,
    const float* __restrict__ wq, const float* __restrict__ wk, const float* __restrict__ wv,
    const float* __restrict__ wo, const float* __restrict__ pe)
{
    int y = blockIdx.y;
    int i = blockIdx.x * blockDim.x + threadIdx.x;
    if (y < 3) {
        int n4 = M * D / 4;
        if (i >= n4) return;
        const float* src = (y == 0) ? q : (y == 1) ? k : v;
        size_t off = OFF_QH + (size_t)y * M * D;
        float4 val = reinterpret_cast<const float4*>(src)[i];
        __half2* d = reinterpret_cast<__half2*>(g_buf + off) + 2 * i;
        d[0] = __floats2half2_rn(val.x, val.y);
        d[1] = __floats2half2_rn(val.z, val.w);
    } else if (y < 7) {
        int n4 = D * D / 4;
        if (i >= n4) return;
        const float* src = (y == 3) ? wq : (y == 4) ? wk : (y == 5) ? wv : wo;
        size_t off = OFF_WQ + (size_t)(y - 3) * D * D;
        float4 val = reinterpret_cast<const float4*>(src)[i];
        __half2* d = reinterpret_cast<__half2*>(g_buf + off) + 2 * i;
        d[0] = __floats2half2_rn(val.x, val.y);
        d[1] = __floats2half2_rn(val.z, val.w);
    } else {
        if (i >= S * DK) return;
        int r = i >> 6, d = i & 63;
        g_buf[OFF_PE + i] = __float2half(pe[((size_t)(S - 1 - r) << 6) + d]);
    }
}

// ============================ GEMM body ============================
// C[M,1024] = (A[M,1024] @ Bw[1024,1024] + bias) * scale.
// BK=32 per stage, 3-stage cp.async pipeline, ONE __syncthreads per k-iter.
// Sized for 3 CTAs/SM: smem 56.8KB/CTA, __launch_bounds__(256,3) caps regs.
// MODE 0: fp16 -> head layout [bh][s][dk] at g_buf+dst_off; MODE 1: fp32 -> outf
constexpr int GS_A = 128 * 40;   // halves per A stage
constexpr int GS_B = 32 * 136;   // halves per B stage
constexpr int GEMM_SMEM = 3 * (GS_A + GS_B) * 2;  // 56,832 bytes

template<int MODE>
DINL void gemm_body(size_t a_off, size_t b_off, const float* __restrict__ bias,
                    float scale, size_t dst_off, float* __restrict__ outf)
{
    extern __shared__ __half gsm[];
    __half* As = gsm;                 // [3][128][40]
    __half* Bs = gsm + 3 * GS_A;      // [3][32][136]
    const __half* A  = g_buf + a_off;
    const __half* Bw = g_buf + b_off;
    int tid = threadIdx.x, lane = tid & 31, wid = tid >> 5;
    int wm = wid & 3, wn = wid >> 2;
    int m0 = blockIdx.y * 128, n0 = blockIdx.x * 128;

    // precomputed ldmatrix base addresses (shared space, bytes)
    unsigned smem_u = (unsigned)__cvta_generic_to_shared(gsm);
    unsigned aBase = smem_u +
        ((unsigned)((wm * 32 + (lane & 15)) * 40 + ((lane >> 4) << 3)) << 1);
    unsigned bBase = smem_u + (unsigned)(3 * GS_A * 2) +
        ((unsigned)((lane & 15) * 136 + wn * 64 + ((lane >> 4) << 3)) << 1);

    auto load_stage = [&](int st, int kb) {
        __half* Ad = As + st * GS_A;
        __half* Bd = Bs + st * GS_B;
#pragma unroll
        for (int i = 0; i < 2; i++) {
            int idx = tid + i * 256;
            int r = idx >> 2, c = (idx & 3) * 8;
            cp_async16(Ad + r * 40 + c, A + (size_t)(m0 + r) * 1024 + kb * 32 + c);
        }
#pragma unroll
        for (int i = 0; i < 2; i++) {
            int idx = tid + i * 256;
            int r = idx >> 4, c = (idx & 15) * 8;
            cp_async16(Bd + r * 136 + c, Bw + (size_t)(kb * 32 + r) * 1024 + n0 + c);
        }
        asm volatile("cp.async.commit_group;");
    };

    float acc[2][8][4] = {};
    load_stage(0, 0);
    load_stage(1, 1);

    int scur = 0, sn2 = 2;
    for (int kb = 0; kb < 32; kb++) {
        asm volatile("cp.async.wait_group 1;");
        __syncthreads();
        if (kb < 30) load_stage(sn2, kb + 2);
        else asm volatile("cp.async.commit_group;");

        unsigned aAddr = aBase + (unsigned)(scur * (GS_A * 2));
        unsigned bAddr = bBase + (unsigned)(scur * (GS_B * 2));
#pragma unroll
        for (int kk = 0; kk < 2; kk++) {
            unsigned a[2][4];
#pragma unroll
            for (int mb = 0; mb < 2; mb++)
                ldsm_a_u(a[mb], aAddr + mb * (16 * 40 * 2) + kk * 32);
#pragma unroll
            for (int nb2 = 0; nb2 < 4; nb2++) {
                unsigned b[4];
                ldsm_bt_u(b, bAddr + kk * (16 * 136 * 2) + nb2 * 32);
#pragma unroll
                for (int mb = 0; mb < 2; mb++) {
                    mma16816(acc[mb][2 * nb2],     a[mb], b[0], b[1]);
                    mma16816(acc[mb][2 * nb2 + 1], a[mb], b[2], b[3]);
                }
            }
        }
        scur = (scur == 2) ? 0 : scur + 1;
        sn2  = (sn2  == 2) ? 0 : sn2  + 1;
    }
#pragma unroll
    for (int mb = 0; mb < 2; mb++) {
#pragma unroll
        for (int nb = 0; nb < 8; nb++) {
            int mr = m0 + wm * 32 + mb * 16 + (lane >> 2);
            int nc = n0 + wn * 64 + nb * 8 + (lane & 3) * 2;
            float b0 = bias[nc], b1 = bias[nc + 1];
            float v00 = (acc[mb][nb][0] + b0) * scale, v01 = (acc[mb][nb][1] + b1) * scale;
            float v10 = (acc[mb][nb][2] + b0) * scale, v11 = (acc[mb][nb][3] + b1) * scale;
            if (MODE == 0) {
                int bb = mr >> 11, s = mr & 2047, h = nc >> 6, d = nc & 63;
                __half* dst = g_buf + dst_off +
                              ((size_t)(bb * 16 + h) * 2048 + s) * 64 + d;
                *reinterpret_cast<__half2*>(dst)       = __floats2half2_rn(v00, v01);
                *reinterpret_cast<__half2*>(dst + 512) = __floats2half2_rn(v10, v11);
            } else {
                float* dst = outf + (size_t)mr * 1024 + nc;
                dst[0] = v00; dst[1] = v01;
                dst += 8 * 1024;
                dst[0] = v10; dst[1] = v11;
            }
        }
    }
}

__global__ __launch_bounds__(256, 3) void gemm_qkv_kernel(
    const float* __restrict__ bq, const float* __restrict__ bk, const float* __restrict__ bv)
{
    int z = blockIdx.z;
    size_t ao  = (z == 0) ? OFF_QH : (z == 1) ? OFF_KH : OFF_VH;
    size_t bwo = (z == 0) ? OFF_WQ : (z == 1) ? OFF_WK : OFF_WV;
    const float* bias = (z == 0) ? bq : (z == 1) ? bk : bv;
    size_t dst = (z == 0) ? OFF_Q : (z == 1) ? OFF_K : OFF_V;
    float scale = (z == 0) ? 0.125f : 1.0f;   // fold 1/sqrt(dk) into Q (exact in fp16)
    gemm_body<0>(ao, bwo, bias, scale, dst, nullptr);
}

__global__ __launch_bounds__(256, 3) void gemm_o_kernel(const float* __restrict__ bo,
                                                        float* __restrict__ out)
{
    gemm_body<1>(OFF_AO, OFF_WO, bo, 1.0f, 0, out);
}

// ============================ attention ============================
// Rolling PE window: slot = r & 127. Window invariant at start of iter kt
// (C = qs - kt*64): PEs holds rows [C-64, C+63]. Pos MMA computes the 64 new
// slots; first iter computes all 128. PE prefetch for the next iter is issued
// AFTER the pos MMA (kt==0 guarded by __syncthreads). Q pre-scaled by 1/8.
constexpr int ATTN_SMEM = 64 * 72 * 2        // Qs
                        + 2 * 64 * 72 * 2    // Ks[2]
                        + 2 * 64 * 72 * 2    // Vs[2]
                        + 128 * 72 * 2       // PEs (slot-indexed)
                        + 64 * 132 * 4;      // Ps fp32

__global__ __launch_bounds__(128) void attn_kernel() {
    extern __shared__ char smraw[];
    __half* Qs  = (__half*)smraw;            // [64][72]
    __half* Ks  = Qs + 64 * 72;              // [2][64][72]
    __half* Vs  = Ks + 2 * 64 * 72;          // [2][64][72]
    __half* PEs = Vs + 2 * 64 * 72;          // [128][72]  slot = r & 127
    float*  Ps  = (float*)(PEs + 128 * 72);  // [64][132]

    int tid = threadIdx.x, lane = tid & 31, w = tid >> 5;
    int qt = blockIdx.x, bh = blockIdx.y;
    int qs = qt * 64;

    const __half* Qg     = g_buf + OFF_Q + ((size_t)bh * S + qs) * DK;
    const __half* Kbase  = g_buf + OFF_K + (size_t)bh * S * DK;
    const __half* Vbase  = g_buf + OFF_V + (size_t)bh * S * DK;
    const __half* PEbase = g_buf + OFF_PE;

    // prologue: Q, K/V tile 0, PE full window (rows [qs-64, qs+63])
#pragma unroll
    for (int it = 0; it < 4; it++) {
        int idx = tid + it * 128;
        int r = idx >> 3, c = (idx & 7) * 8;
        cp_async16(Qs + r * 72 + c, Qg + (size_t)r * 64 + c);
        cp_async16(Ks + r * 72 + c, Kbase + (size_t)r * 64 + c);
        cp_async16(Vs + r * 72 + c, Vbase + (size_t)r * 64 + c);
    }
    {
        int rb = qs - 64;
#pragma unroll
        for (int it = 0; it < 8; it++) {
            int idx = tid + it * 128;
            int rr = idx >> 3, c = (idx & 7) * 8;
            int r = rb + rr;
            int rc = r < 0 ? 0 : r;
            int slot = r & 127;
            cp_async16(PEs + slot * 72 + c, PEbase + (size_t)rc * 64 + c);
        }
    }
    asm volatile("cp.async.commit_group;");
    asm volatile("cp.async.wait_group 0;");
    __syncthreads();

    unsigned aq[4][4];
#pragma unroll
    for (int kk = 0; kk < 4; kk++)
        ldsm_a(aq[kk], Qs + (w * 16 + (lane & 15)) * 72 + kk * 16 + ((lane >> 4) << 3));

    float m0v = -1e30f, m1v = -1e30f, l0 = 0.f, l1 = 0.f;
    float ao[8][4] = {};
    int i0 = w * 16 + (lane >> 2);

    for (int kt = 0; kt <= qt; kt++) {
        int st = kt & 1;
        int ks = kt * 64;

        // K/V prefetch for next tile (disjoint buffer -> safe to issue now)
        if (kt < qt) {
            int ks1 = ks + 64;
            int sn = st ^ 1;
#pragma unroll
            for (int it = 0; it < 4; it++) {
                int idx = tid + it * 128;
                int r = idx >> 3, c = (idx & 7) * 8;
                cp_async16(Ks + sn * 64 * 72 + r * 72 + c,
                           Kbase + (size_t)(ks1 + r) * 64 + c);
                cp_async16(Vs + sn * 64 * 72 + r * 72 + c,
                           Vbase + (size_t)(ks1 + r) * 64 + c);
            }
            asm volatile("cp.async.commit_group;");
        }

        const __half* Kcur = Ks + st * 64 * 72;
        const __half* Vcur = Vs + st * 64 * 72;

        // S = Q @ K^T (16x64 per warp)
        float sc[8][4] = {};
#pragma unroll
        for (int kk = 0; kk < 4; kk++) {
#pragma unroll
            for (int nb2 = 0; nb2 < 4; nb2++) {
                unsigned bk[4];
                ldsm_a(bk, Kcur + (nb2 * 16 + (lane & 7) + ((lane >> 4) << 3)) * 72 +
                               kk * 16 + (((lane >> 3) & 1) << 3));
                mma16816(sc[2 * nb2],     aq[kk], bk[0], bk[1]);
                mma16816(sc[2 * nb2 + 1], aq[kk], bk[2], bk[3]);
            }
        }

        // pos = Q @ PE^T for the NEW slots (all 128 on first iter)
        {
            int bstart = (kt == 0) ? 0 : ((qs - ks - 64) & 127);
            int nblk   = (kt == 0) ? 8 : 4;
#pragma unroll 4
            for (int nb2 = 0; nb2 < nblk; nb2++) {
                int colb = bstart + nb2 * 16;
                float pp[2][4] = {};
#pragma unroll
                for (int kk = 0; kk < 4; kk++) {
                    unsigned bp[4];
                    ldsm_a(bp, PEs + (colb + (lane & 7) + ((lane >> 4) << 3)) * 72 +
                                     kk * 16 + (((lane >> 3) & 1) << 3));
                    mma16816(pp[0], aq[kk], bp[0], bp[1]);
                    mma16816(pp[1], aq[kk], bp[2], bp[3]);
                }
                int cb = colb + (lane & 3) * 2;
                Ps[i0 * 132 + cb]           = pp[0][0];
                Ps[i0 * 132 + cb + 1]       = pp[0][1];
                Ps[(i0 + 8) * 132 + cb]     = pp[0][2];
                Ps[(i0 + 8) * 132 + cb + 1] = pp[0][3];
                Ps[i0 * 132 + cb + 8]       = pp[1][0];
                Ps[i0 * 132 + cb + 9]       = pp[1][1];
                Ps[(i0 + 8) * 132 + cb + 8] = pp[1][2];
                Ps[(i0 + 8) * 132 + cb + 9] = pp[1][3];
            }
        }

        // PE prefetch for next tile — AFTER pos MMA. At kt==0 the pos MMA read
        // ALL slots incl. the ones we now overwrite: guard with syncthreads.
        if (kt < qt) {
            if (kt == 0) __syncthreads();
            int rb2 = qs - ks - 128;  // rows [C-128, C-65] -> slots [C&127 ..]
#pragma unroll
            for (int it = 0; it < 4; it++) {
                int idx = tid + it * 128;
                int rr = idx >> 3, c = (idx & 7) * 8;
                int r = rb2 + rr;
                int rc = r < 0 ? 0 : r;
                int slot = r & 127;
                cp_async16(PEs + slot * 72 + c, PEbase + (size_t)rc * 64 + c);
            }
            asm volatile("cp.async.commit_group;");
        }
        __syncwarp();

        // combine + mask + online softmax (scale already folded into Q)
        int Cc = qs - ks;
        float mx0 = -1e30f, mx1 = -1e30f;
#pragma unroll
        for (int nb = 0; nb < 8; nb++) {
#pragma unroll
            for (int e = 0; e < 4; e++) {
                int i = (e < 2) ? i0 : i0 + 8;
                int j = nb * 8 + (lane & 3) * 2 + (e & 1);
                int sIdx = (Cc + i - j) & 127;
                float v = sc[nb][e] + Ps[i * 132 + sIdx];
                if (kt == qt && j > i) v = -1e30f;
                sc[nb][e] = v;
                if (e < 2) mx0 = fmaxf(mx0, v); else mx1 = fmaxf(mx1, v);
            }
        }
        mx0 = fmaxf(mx0, __shfl_xor_sync(0xffffffffu, mx0, 1));
        mx0 = fmaxf(mx0, __shfl_xor_sync(0xffffffffu, mx0, 2));
        mx1 = fmaxf(mx1, __shfl_xor_sync(0xffffffffu, mx1, 1));
        mx1 = fmaxf(mx1, __shfl_xor_sync(0xffffffffu, mx1, 2));
        float mn0 = fmaxf(m0v, mx0), mn1 = fmaxf(m1v, mx1);
        float c0 = __expf(m0v - mn0), c1 = __expf(m1v - mn1);
        float rs0 = 0.f, rs1 = 0.f;
#pragma unroll
        for (int nb = 0; nb < 8; nb++) {
#pragma unroll
            for (int e = 0; e < 4; e++) {
                float p = __expf(sc[nb][e] - ((e < 2) ? mn0 : mn1));
                sc[nb][e] = p;
                if (e < 2) rs0 += p; else rs1 += p;
            }
        }
        rs0 += __shfl_xor_sync(0xffffffffu, rs0, 1);
        rs0 += __shfl_xor_sync(0xffffffffu, rs0, 2);
        rs1 += __shfl_xor_sync(0xffffffffu, rs1, 1);
        rs1 += __shfl_xor_sync(0xffffffffu, rs1, 2);
        l0 = l0 * c0 + rs0;  l1 = l1 * c1 + rs1;
        m0v = mn0;  m1v = mn1;
#pragma unroll
        for (int nb = 0; nb < 8; nb++) {
            ao[nb][0] *= c0; ao[nb][1] *= c0;
            ao[nb][2] *= c1; ao[nb][3] *= c1;
        }

        // repack P (C-frag) -> A-frag, then O += P @ V
        unsigned pa[4][4];
#pragma unroll
        for (int kb = 0; kb < 4; kb++) {
            pa[kb][0] = packh2(sc[2 * kb][0],     sc[2 * kb][1]);
            pa[kb][1] = packh2(sc[2 * kb][2],     sc[2 * kb][3]);
            pa[kb][2] = packh2(sc[2 * kb + 1][0], sc[2 * kb + 1][1]);
            pa[kb][3] = packh2(sc[2 * kb + 1][2], sc[2 * kb + 1][3]);
        }
#pragma unroll
        for (int kb = 0; kb < 4; kb++) {
#pragma unroll
            for (int nb2 = 0; nb2 < 4; nb2++) {
                unsigned bv[4];
                ldsm_bt(bv, Vcur + (kb * 16 + (lane & 15)) * 72 +
                                nb2 * 16 + ((lane >> 4) << 3));
                mma16816(ao[2 * nb2],     pa[kb], bv[0], bv[1]);
                mma16816(ao[2 * nb2 + 1], pa[kb], bv[2], bv[3]);
            }
        }

        if (kt < qt) asm volatile("cp.async.wait_group 0;");
        __syncthreads();
    }

    // epilogue: O /= l, write to AO [b*S+s][h*64+d]
    int bb = bh >> 4, h = bh & 15;
    float inv0 = 1.f / l0, inv1 = 1.f / l1;
#pragma unroll
    for (int nb = 0; nb < 8; nb++) {
        int j = nb * 8 + (lane & 3) * 2;
        int col = h * 64 + j;
        __half* dst0 = g_buf + OFF_AO + ((size_t)(bb * S + qs + i0)) * 1024 + col;
        *reinterpret_cast<__half2*>(dst0) =
            __floats2half2_rn(ao[nb][0] * inv0, ao[nb][1] * inv0);
        __half* dst1 = dst0 + (size_t)8 * 1024;
        *reinterpret_cast<__half2*>(dst1) =
            __floats2half2_rn(ao[nb][2] * inv1, ao[nb][3] * inv1);
    }
}

// ============================ launch ============================
extern "C" void kernel_launch(void* const* d_in, const int* in_sizes, int n_in,
                              void* d_out, int out_size) {
    const float* query = (const float*)d_in[0];
    const float* key   = (const float*)d_in[1];
    const float* value = (const float*)d_in[2];
    const float* pe    = (const float*)d_in[3];
    const float* Wq = (const float*)d_in[4];
    const float* bq = (const float*)d_in[5];
    const float* Wk = (const float*)d_in[6];
    const float* bk = (const float*)d_in[7];
    const float* Wv = (const float*)d_in[8];
    const float* bv = (const float*)d_in[9];
    const float* Wo = (const float*)d_in[10];
    const float* bo = (const float*)d_in[11];

    cudaFuncSetAttribute(attn_kernel, cudaFuncAttributeMaxDynamicSharedMemorySize, ATTN_SMEM);
    cudaFuncSetAttribute(gemm_qkv_kernel, cudaFuncAttributeMaxDynamicSharedMemorySize, GEMM_SMEM);
    cudaFuncSetAttribute(gemm_o_kernel, cudaFuncAttributeMaxDynamicSharedMemorySize, GEMM_SMEM);

    convert_all_kernel<<<dim3(4096, 8), 256>>>(query, key, value, Wq, Wk, Wv, Wo, pe);

    gemm_qkv_kernel<<<dim3(8, 32, 3), 256, GEMM_SMEM>>>(bq, bk, bv);

    dim3 agrid(S / 64, NBATCH * H);
    attn_kernel<<<agrid, 128, ATTN_SMEM>>>();

    gemm_o_kernel<<<dim3(8, 32), 256, GEMM_SMEM>>>(bo, (float*)d_out);
}

// round 10
// speedup vs baseline: 1.2781x; 1.2781x over previous
#include <cuda_runtime.h>
#include <cuda_fp16.h>

#define DINL __device__ __forceinline__

constexpr int S = 2048, D = 1024, H = 16, NBATCH = 2, DK = 64;
constexpr int M = NBATCH * S;  // 4096 rows

// ---- scratch offsets (halves) ----
constexpr size_t OFF_QH = 0;
constexpr size_t OFF_KH = OFF_QH + (size_t)M * D;
constexpr size_t OFF_VH = OFF_KH + (size_t)M * D;
constexpr size_t OFF_WQ = OFF_VH + (size_t)M * D;
constexpr size_t OFF_WK = OFF_WQ + (size_t)D * D;
constexpr size_t OFF_WV = OFF_WK + (size_t)D * D;
constexpr size_t OFF_WO = OFF_WV + (size_t)D * D;
constexpr size_t OFF_PE = OFF_WO + (size_t)D * D;     // pe_rev [S][64]
constexpr size_t OFF_Q  = OFF_PE + (size_t)S * DK;    // [bh][s][dk] (pre-scaled by 1/8)
constexpr size_t OFF_K  = OFF_Q + (size_t)M * D;
constexpr size_t OFF_V  = OFF_K + (size_t)M * D;
constexpr size_t OFF_AO = OFF_V + (size_t)M * D;      // [b*S+s][h*64+d]
constexpr size_t BUF_TOTAL = OFF_AO + (size_t)M * D;

__device__ __align__(256) __half g_buf[BUF_TOTAL];

// ---- PTX helpers ----
DINL void ldsm_a(unsigned (&r)[4], const void* p) {
    unsigned a = (unsigned)__cvta_generic_to_shared(p);
    asm volatile("ldmatrix.sync.aligned.m8n8.x4.shared.b16 {%0,%1,%2,%3}, [%4];"
                 : "=r"(r[0]), "=r"(r[1]), "=r"(r[2]), "=r"(r[3]) : "r"(a));
}
DINL void ldsm_a_u(unsigned (&r)[4], unsigned a) {
    asm volatile("ldmatrix.sync.aligned.m8n8.x4.shared.b16 {%0,%1,%2,%3}, [%4];"
                 : "=r"(r[0]), "=r"(r[1]), "=r"(r[2]), "=r"(r[3]) : "r"(a));
}
DINL void ldsm_bt(unsigned (&r)[4], const void* p) {
    unsigned a = (unsigned)__cvta_generic_to_shared(p);
    asm volatile("ldmatrix.sync.aligned.m8n8.x4.trans.shared.b16 {%0,%1,%2,%3}, [%4];"
                 : "=r"(r[0]), "=r"(r[1]), "=r"(r[2]), "=r"(r[3]) : "r"(a));
}
DINL void ldsm_bt_u(unsigned (&r)[4], unsigned a) {
    asm volatile("ldmatrix.sync.aligned.m8n8.x4.trans.shared.b16 {%0,%1,%2,%3}, [%4];"
                 : "=r"(r[0]), "=r"(r[1]), "=r"(r[2]), "=r"(r[3]) : "r"(a));
}
DINL void mma16816(float (&c)[4], const unsigned (&a)[4], unsigned b0, unsigned b1) {
    asm volatile(
        "mma.sync.aligned.m16n8k16.row.col.f32.f16.f16.f32 "
        "{%0,%1,%2,%3}, {%4,%5,%6,%7}, {%8,%9}, {%0,%1,%2,%3};"
        : "+f"(c[0]), "+f"(c[1]), "+f"(c[2]), "+f"(c[3])
        : "r"(a[0]), "r"(a[1]), "r"(a[2]), "r"(a[3]), "r"(b0), "r"(b1));
}
DINL unsigned packh2(float x, float y) {
    __half2 h = __floats2half2_rn(x, y);
    return *reinterpret_cast<unsigned*>(&h);
}
DINL void cp_async16(void* dst, const void* src) {
    unsigned d = (unsigned)__cvta_generic_to_shared(dst);
    asm volatile("cp.async.cg.shared.global [%0], [%1], 16;" :: "r"(d), "l"(src));
}

// ============================ fused converts ============================
__global__ void convert_all_kernel(
    const float* __restrict__ q, const float* __restrict__ k, const float* __restrict__ v,
    const float* __restrict__ wq, const float* __restrict__ wk, const float* __restrict__ wv,
    const float* __restrict__ wo, const float* __restrict__ pe)
{
    int y = blockIdx.y;
    int i = blockIdx.x * blockDim.x + threadIdx.x;
    if (y < 3) {
        int n4 = M * D / 4;
        if (i >= n4) return;
        const float* src = (y == 0) ? q : (y == 1) ? k : v;
        size_t off = OFF_QH + (size_t)y * M * D;
        float4 val = reinterpret_cast<const float4*>(src)[i];
        __half2* d = reinterpret_cast<__half2*>(g_buf + off) + 2 * i;
        d[0] = __floats2half2_rn(val.x, val.y);
        d[1] = __floats2half2_rn(val.z, val.w);
    } else if (y < 7) {
        int n4 = D * D / 4;
        if (i >= n4) return;
        const float* src = (y == 3) ? wq : (y == 4) ? wk : (y == 5) ? wv : wo;
        size_t off = OFF_WQ + (size_t)(y - 3) * D * D;
        float4 val = reinterpret_cast<const float4*>(src)[i];
        __half2* d = reinterpret_cast<__half2*>(g_buf + off) + 2 * i;
        d[0] = __floats2half2_rn(val.x, val.y);
        d[1] = __floats2half2_rn(val.z, val.w);
    } else {
        if (i >= S * DK) return;
        int r = i >> 6, d = i & 63;
        g_buf[OFF_PE + i] = __float2half(pe[((size_t)(S - 1 - r) << 6) + d]);
    }
}

// ============================ GEMM body (R6: BK=64, 3-stage, 1 barrier/iter) ============================
constexpr int GS_A = 128 * 72;   // halves per A stage
constexpr int GS_B = 64 * 136;   // halves per B stage
constexpr int GEMM_SMEM = 3 * (GS_A + GS_B) * 2;  // 107,520 bytes

template<int MODE>
DINL void gemm_body(size_t a_off, size_t b_off, const float* __restrict__ bias,
                    float scale, size_t dst_off, float* __restrict__ outf)
{
    extern __shared__ __half gsm[];
    __half* As = gsm;                 // [3][128][72]
    __half* Bs = gsm + 3 * GS_A;      // [3][64][136]
    const __half* A  = g_buf + a_off;
    const __half* Bw = g_buf + b_off;
    int tid = threadIdx.x, lane = tid & 31, wid = tid >> 5;
    int wm = wid & 3, wn = wid >> 2;
    int m0 = blockIdx.y * 128, n0 = blockIdx.x * 128;

    auto load_stage = [&](int st, int kb) {
        __half* Ad = As + st * GS_A;
        __half* Bd = Bs + st * GS_B;
#pragma unroll
        for (int i = 0; i < 4; i++) {
            int idx = tid + i * 256;
            int r = idx >> 3, c = (idx & 7) * 8;
            cp_async16(Ad + r * 72 + c, A + (size_t)(m0 + r) * 1024 + kb * 64 + c);
        }
#pragma unroll
        for (int i = 0; i < 4; i++) {
            int idx = tid + i * 256;
            int r = idx >> 4, c = (idx & 15) * 8;
            cp_async16(Bd + r * 136 + c, Bw + (size_t)(kb * 64 + r) * 1024 + n0 + c);
        }
        asm volatile("cp.async.commit_group;");
    };

    float acc[2][8][4] = {};
    load_stage(0, 0);
    load_stage(1, 1);

    for (int kb = 0; kb < 16; kb++) {
        asm volatile("cp.async.wait_group 1;");
        __syncthreads();
        if (kb + 2 < 16) load_stage((kb + 2) % 3, kb + 2);
        else asm volatile("cp.async.commit_group;");

        const __half* Ac = As + (kb % 3) * GS_A;
        const __half* Bc = Bs + (kb % 3) * GS_B;
#pragma unroll
        for (int kk = 0; kk < 4; kk++) {
            unsigned a[2][4];
#pragma unroll
            for (int mb = 0; mb < 2; mb++)
                ldsm_a(a[mb], Ac + (wm * 32 + mb * 16 + (lane & 15)) * 72 +
                              kk * 16 + ((lane >> 4) << 3));
#pragma unroll
            for (int nb2 = 0; nb2 < 4; nb2++) {
                unsigned b[4];
                ldsm_bt(b, Bc + (kk * 16 + (lane & 15)) * 136 + wn * 64 +
                           nb2 * 16 + ((lane >> 4) << 3));
#pragma unroll
                for (int mb = 0; mb < 2; mb++) {
                    mma16816(acc[mb][2 * nb2],     a[mb], b[0], b[1]);
                    mma16816(acc[mb][2 * nb2 + 1], a[mb], b[2], b[3]);
                }
            }
        }
    }
#pragma unroll
    for (int mb = 0; mb < 2; mb++) {
#pragma unroll
        for (int nb = 0; nb < 8; nb++) {
            int mr = m0 + wm * 32 + mb * 16 + (lane >> 2);
            int nc = n0 + wn * 64 + nb * 8 + (lane & 3) * 2;
            float b0 = bias[nc], b1 = bias[nc + 1];
            float v00 = (acc[mb][nb][0] + b0) * scale, v01 = (acc[mb][nb][1] + b1) * scale;
            float v10 = (acc[mb][nb][2] + b0) * scale, v11 = (acc[mb][nb][3] + b1) * scale;
            if (MODE == 0) {
                int bb = mr >> 11, s = mr & 2047, h = nc >> 6, d = nc & 63;
                __half* dst = g_buf + dst_off +
                              ((size_t)(bb * 16 + h) * 2048 + s) * 64 + d;
                *reinterpret_cast<__half2*>(dst)       = __floats2half2_rn(v00, v01);
                *reinterpret_cast<__half2*>(dst + 512) = __floats2half2_rn(v10, v11);
            } else {
                float* dst = outf + (size_t)mr * 1024 + nc;
                dst[0] = v00; dst[1] = v01;
                dst += 8 * 1024;
                dst[0] = v10; dst[1] = v11;
            }
        }
    }
}

__global__ __launch_bounds__(256) void gemm_qkv_kernel(
    const float* __restrict__ bq, const float* __restrict__ bk, const float* __restrict__ bv)
{
    int z = blockIdx.z;
    size_t ao  = (z == 0) ? OFF_QH : (z == 1) ? OFF_KH : OFF_VH;
    size_t bwo = (z == 0) ? OFF_WQ : (z == 1) ? OFF_WK : OFF_WV;
    const float* bias = (z == 0) ? bq : (z == 1) ? bk : bv;
    size_t dst = (z == 0) ? OFF_Q : (z == 1) ? OFF_K : OFF_V;
    float scale = (z == 0) ? 0.125f : 1.0f;   // fold 1/sqrt(dk) into Q (exact in fp16)
    gemm_body<0>(ao, bwo, bias, scale, dst, nullptr);
}

__global__ __launch_bounds__(256) void gemm_o_kernel(const float* __restrict__ bo,
                                                     float* __restrict__ out)
{
    gemm_body<1>(OFF_AO, OFF_WO, bo, 1.0f, 0, out);
}

// ============================ attention ============================
// Rolling PE window (slot = r & 127), fp16 Ps, Ps overlaid on Qs region.
// smem: Ks[2][64][72] | Vs[2][64][72] | PEs[128][72] | PsQ (Qs [64][72] then
// Ps [64][136] fp16). Total 72,704 B -> 3 CTAs/SM.
constexpr int ATTN_SMEM = (2 * 64 * 72 + 2 * 64 * 72 + 128 * 72) * 2 + 64 * 136 * 2;

__global__ __launch_bounds__(128, 3) void attn_kernel() {
    extern __shared__ char smraw[];
    __half* Ks  = (__half*)smraw;            // [2][64][72]
    __half* Vs  = Ks + 2 * 64 * 72;          // [2][64][72]
    __half* PEs = Vs + 2 * 64 * 72;          // [128][72]  slot = r & 127
    __half* Qs  = PEs + 128 * 72;            // [64][72]   (prologue only)
    __half* Ps  = Qs;                        // [64][136]  fp16, overlays Qs

    int tid = threadIdx.x, lane = tid & 31, w = tid >> 5;
    int qt = blockIdx.x, bh = blockIdx.y;
    int qs = qt * 64;

    const __half* Qg     = g_buf + OFF_Q + ((size_t)bh * S + qs) * DK;
    const __half* Kbase  = g_buf + OFF_K + (size_t)bh * S * DK;
    const __half* Vbase  = g_buf + OFF_V + (size_t)bh * S * DK;
    const __half* PEbase = g_buf + OFF_PE;

    // prologue: Q, K/V tile 0, PE full window (rows [qs-64, qs+63])
#pragma unroll
    for (int it = 0; it < 4; it++) {
        int idx = tid + it * 128;
        int r = idx >> 3, c = (idx & 7) * 8;
        cp_async16(Qs + r * 72 + c, Qg + (size_t)r * 64 + c);
        cp_async16(Ks + r * 72 + c, Kbase + (size_t)r * 64 + c);
        cp_async16(Vs + r * 72 + c, Vbase + (size_t)r * 64 + c);
    }
    {
        int rb = qs - 64;
#pragma unroll
        for (int it = 0; it < 8; it++) {
            int idx = tid + it * 128;
            int rr = idx >> 3, c = (idx & 7) * 8;
            int r = rb + rr;
            int rc = r < 0 ? 0 : r;
            int slot = r & 127;
            cp_async16(PEs + slot * 72 + c, PEbase + (size_t)rc * 64 + c);
        }
    }
    asm volatile("cp.async.commit_group;");
    asm volatile("cp.async.wait_group 0;");
    __syncthreads();

    unsigned aq[4][4];
#pragma unroll
    for (int kk = 0; kk < 4; kk++)
        ldsm_a(aq[kk], Qs + (w * 16 + (lane & 15)) * 72 + kk * 16 + ((lane >> 4) << 3));
    __syncthreads();   // all warps have consumed Qs before Ps overlays it

    float m0v = -1e30f, m1v = -1e30f, l0 = 0.f, l1 = 0.f;
    float ao[8][4] = {};
    int i0 = w * 16 + (lane >> 2);

    for (int kt = 0; kt <= qt; kt++) {
        int st = kt & 1;
        int ks = kt * 64;

        // K/V prefetch for next tile (disjoint buffer -> safe to issue now)
        if (kt < qt) {
            int ks1 = ks + 64;
            int sn = st ^ 1;
#pragma unroll
            for (int it = 0; it < 4; it++) {
                int idx = tid + it * 128;
                int r = idx >> 3, c = (idx & 7) * 8;
                cp_async16(Ks + sn * 64 * 72 + r * 72 + c,
                           Kbase + (size_t)(ks1 + r) * 64 + c);
                cp_async16(Vs + sn * 64 * 72 + r * 72 + c,
                           Vbase + (size_t)(ks1 + r) * 64 + c);
            }
            asm volatile("cp.async.commit_group;");
        }

        const __half* Kcur = Ks + st * 64 * 72;
        const __half* Vcur = Vs + st * 64 * 72;

        // S = Q @ K^T (16x64 per warp)
        float sc[8][4] = {};
#pragma unroll
        for (int kk = 0; kk < 4; kk++) {
#pragma unroll
            for (int nb2 = 0; nb2 < 4; nb2++) {
                unsigned bk[4];
                ldsm_a(bk, Kcur + (nb2 * 16 + (lane & 7) + ((lane >> 4) << 3)) * 72 +
                               kk * 16 + (((lane >> 3) & 1) << 3));
                mma16816(sc[2 * nb2],     aq[kk], bk[0], bk[1]);
                mma16816(sc[2 * nb2 + 1], aq[kk], bk[2], bk[3]);
            }
        }

        // pos = Q @ PE^T for the NEW slots (all 128 on first iter), fp16 store
        {
            int bstart = (kt == 0) ? 0 : ((qs - ks - 64) & 127);
            int nblk   = (kt == 0) ? 8 : 4;
#pragma unroll 4
            for (int nb2 = 0; nb2 < nblk; nb2++) {
                int colb = bstart + nb2 * 16;
                float pp[2][4] = {};
#pragma unroll
                for (int kk = 0; kk < 4; kk++) {
                    unsigned bp[4];
                    ldsm_a(bp, PEs + (colb + (lane & 7) + ((lane >> 4) << 3)) * 72 +
                                     kk * 16 + (((lane >> 3) & 1) << 3));
                    mma16816(pp[0], aq[kk], bp[0], bp[1]);
                    mma16816(pp[1], aq[kk], bp[2], bp[3]);
                }
                int cb = colb + (lane & 3) * 2;
                Ps[i0 * 136 + cb]           = __float2half(pp[0][0]);
                Ps[i0 * 136 + cb + 1]       = __float2half(pp[0][1]);
                Ps[(i0 + 8) * 136 + cb]     = __float2half(pp[0][2]);
                Ps[(i0 + 8) * 136 + cb + 1] = __float2half(pp[0][3]);
                Ps[i0 * 136 + cb + 8]       = __float2half(pp[1][0]);
                Ps[i0 * 136 + cb + 9]       = __float2half(pp[1][1]);
                Ps[(i0 + 8) * 136 + cb + 8] = __float2half(pp[1][2]);
                Ps[(i0 + 8) * 136 + cb + 9] = __float2half(pp[1][3]);
            }
        }

        // PE prefetch for next tile — AFTER pos MMA (kt==0 guarded)
        if (kt < qt) {
            if (kt == 0) __syncthreads();
            int rb2 = qs - ks - 128;  // rows [C-128, C-65] -> slots [C&127 ..]
#pragma unroll
            for (int it = 0; it < 4; it++) {
                int idx = tid + it * 128;
                int rr = idx >> 3, c = (idx & 7) * 8;
                int r = rb2 + rr;
                int rc = r < 0 ? 0 : r;
                int slot = r & 127;
                cp_async16(PEs + slot * 72 + c, PEbase + (size_t)rc * 64 + c);
            }
            asm volatile("cp.async.commit_group;");
        }
        __syncwarp();

        // combine + mask + online softmax (scale already folded into Q)
        int Cc = qs - ks;
        float mx0 = -1e30f, mx1 = -1e30f;
#pragma unroll
        for (int nb = 0; nb < 8; nb++) {
#pragma unroll
            for (int e = 0; e < 4; e++) {
                int i = (e < 2) ? i0 : i0 + 8;
                int j = nb * 8 + (lane & 3) * 2 + (e & 1);
                int sIdx = (Cc + i - j) & 127;
                float v = sc[nb][e] + __half2float(Ps[i * 136 + sIdx]);
                if (kt == qt && j > i) v = -1e30f;
                sc[nb][e] = v;
                if (e < 2) mx0 = fmaxf(mx0, v); else mx1 = fmaxf(mx1, v);
            }
        }
        mx0 = fmaxf(mx0, __shfl_xor_sync(0xffffffffu, mx0, 1));
        mx0 = fmaxf(mx0, __shfl_xor_sync(0xffffffffu, mx0, 2));
        mx1 = fmaxf(mx1, __shfl_xor_sync(0xffffffffu, mx1, 1));
        mx1 = fmaxf(mx1, __shfl_xor_sync(0xffffffffu, mx1, 2));
        float mn0 = fmaxf(m0v, mx0), mn1 = fmaxf(m1v, mx1);
        float c0 = __expf(m0v - mn0), c1 = __expf(m1v - mn1);
        float rs0 = 0.f, rs1 = 0.f;
#pragma unroll
        for (int nb = 0; nb < 8; nb++) {
#pragma unroll
            for (int e = 0; e < 4; e++) {
                float p = __expf(sc[nb][e] - ((e < 2) ? mn0 : mn1));
                sc[nb][e] = p;
                if (e < 2) rs0 += p; else rs1 += p;
            }
        }
        rs0 += __shfl_xor_sync(0xffffffffu, rs0, 1);
        rs0 += __shfl_xor_sync(0xffffffffu, rs0, 2);
        rs1 += __shfl_xor_sync(0xffffffffu, rs1, 1);
        rs1 += __shfl_xor_sync(0xffffffffu, rs1, 2);
        l0 = l0 * c0 + rs0;  l1 = l1 * c1 + rs1;
        m0v = mn0;  m1v = mn1;
#pragma unroll
        for (int nb = 0; nb < 8; nb++) {
            ao[nb][0] *= c0; ao[nb][1] *= c0;
            ao[nb][2] *= c1; ao[nb][3] *= c1;
        }

        // repack P (C-frag) -> A-frag, then O += P @ V
        unsigned pa[4][4];
#pragma unroll
        for (int kb = 0; kb < 4; kb++) {
            pa[kb][0] = packh2(sc[2 * kb][0],     sc[2 * kb][1]);
            pa[kb][1] = packh2(sc[2 * kb][2],     sc[2 * kb][3]);
            pa[kb][2] = packh2(sc[2 * kb + 1][0], sc[2 * kb + 1][1]);
            pa[kb][3] = packh2(sc[2 * kb + 1][2], sc[2 * kb + 1][3]);
        }
#pragma unroll
        for (int kb = 0; kb < 4; kb++) {
#pragma unroll
            for (int nb2 = 0; nb2 < 4; nb2++) {
                unsigned bv[4];
                ldsm_bt(bv, Vcur + (kb * 16 + (lane & 15)) * 72 +
                                nb2 * 16 + ((lane >> 4) << 3));
                mma16816(ao[2 * nb2],     pa[kb], bv[0], bv[1]);
                mma16816(ao[2 * nb2 + 1], pa[kb], bv[2], bv[3]);
            }
        }

        if (kt < qt) asm volatile("cp.async.wait_group 0;");
        __syncthreads();
    }

    // epilogue: O /= l, write to AO [b*S+s][h*64+d]
    int bb = bh >> 4, h = bh & 15;
    float inv0 = 1.f / l0, inv1 = 1.f / l1;
#pragma unroll
    for (int nb = 0; nb < 8; nb++) {
        int j = nb * 8 + (lane & 3) * 2;
        int col = h * 64 + j;
        __half* dst0 = g_buf + OFF_AO + ((size_t)(bb * S + qs + i0)) * 1024 + col;
        *reinterpret_cast<__half2*>(dst0) =
            __floats2half2_rn(ao[nb][0] * inv0, ao[nb][1] * inv0);
        __half* dst1 = dst0 + (size_t)8 * 1024;
        *reinterpret_cast<__half2*>(dst1) =
            __floats2half2_rn(ao[nb][2] * inv1, ao[nb][3] * inv1);
    }
}

// ============================ launch ============================
extern "C" void kernel_launch(void* const* d_in, const int* in_sizes, int n_in,
                              void* d_out, int out_size) {
    const float* query = (const float*)d_in[0];
    const float* key   = (const float*)d_in[1];
    const float* value = (const float*)d_in[2];
    const float* pe    = (const float*)d_in[3];
    const float* Wq = (const float*)d_in[4];
    const float* bq = (const float*)d_in[5];
    const float* Wk = (const float*)d_in[6];
    const float* bk = (const float*)d_in[7];
    const float* Wv = (const float*)d_in[8];
    const float* bv = (const float*)d_in[9];
    const float* Wo = (const float*)d_in[10];
    const float* bo = (const float*)d_in[11];

    cudaFuncSetAttribute(attn_kernel, cudaFuncAttributeMaxDynamicSharedMemorySize, ATTN_SMEM);
    cudaFuncSetAttribute(gemm_qkv_kernel, cudaFuncAttributeMaxDynamicSharedMemorySize, GEMM_SMEM);
    cudaFuncSetAttribute(gemm_o_kernel, cudaFuncAttributeMaxDynamicSharedMemorySize, GEMM_SMEM);

    convert_all_kernel<<<dim3(4096, 8), 256>>>(query, key, value, Wq, Wk, Wv, Wo, pe);

    gemm_qkv_kernel<<<dim3(8, 32, 3), 256, GEMM_SMEM>>>(bq, bk, bv);

    dim3 agrid(S / 64, NBATCH * H);
    attn_kernel<<<agrid, 128, ATTN_SMEM>>>();

    gemm_o_kernel<<<dim3(8, 32), 256, GEMM_SMEM>>>(bo, (float*)d_out);
}